// round 4
// baseline (speedup 1.0000x reference)
#include <cuda_runtime.h>
#include <cuda_bf16.h>
#include <cstdint>

#define DH 384
#define DG 192
#define TT 48
#define BB 96
#define NTH 384
#define NW 12
#define CL 8            // cluster size = batches per cluster
#define SL 48           // output slice per CTA (DH / CL)
#define LAM 0.9f
#define ETA 0.5f
#define LN_EPS 1e-5f

// ---------------- device scratch (allocation-free rule) ----------------
__device__ float WT_g[DH * DH];              // W_h transposed: WT[j*DH + o] = W_h[o*DH + j]
__device__ float WGT_g[DG * DH];             // W_g transposed
__device__ float ZP_g[(size_t)TT * BB * DH]; // z @ W_g^T + b_h

// ---------------- small helpers ----------------
__device__ __forceinline__ uint32_t smem_addr_u32(const void* p) {
    return (uint32_t)__cvta_generic_to_shared(p);
}
__device__ __forceinline__ uint32_t mapa_u32(uint32_t addr, uint32_t rank) {
    uint32_t r;
    asm("mapa.shared::cluster.u32 %0, %1, %2;" : "=r"(r) : "r"(addr), "r"(rank));
    return r;
}
__device__ __forceinline__ void st_cluster_f32(uint32_t addr, float v) {
    asm volatile("st.shared::cluster.f32 [%0], %1;" :: "r"(addr), "f"(v) : "memory");
}
__device__ __forceinline__ void cluster_sync_() {
    asm volatile("barrier.cluster.arrive.aligned;" ::: "memory");
    asm volatile("barrier.cluster.wait.aligned;" ::: "memory");
}
__device__ __forceinline__ unsigned long long fma2(unsigned long long a,
                                                   unsigned long long b,
                                                   unsigned long long c) {
    unsigned long long d;
    asm("fma.rn.f32x2 %0, %1, %2, %3;" : "=l"(d) : "l"(a), "l"(b), "l"(c));
    return d;
}
__device__ __forceinline__ unsigned long long pack2(float lo, float hi) {
    unsigned long long d;
    asm("mov.b64 %0, {%1, %2};" : "=l"(d) : "f"(lo), "f"(hi));
    return d;
}
__device__ __forceinline__ float2 unpack2(unsigned long long v) {
    float lo, hi;
    asm("mov.b64 {%0, %1}, %2;" : "=f"(lo), "=f"(hi) : "l"(v));
    return make_float2(lo, hi);
}

// ---------------- transpose prep ----------------
__global__ void transpose_k(const float* __restrict__ src, int rows, int cols, int which) {
    __shared__ float tile[32][33];
    float* dst = (which == 0) ? WT_g : WGT_g;
    int c0 = blockIdx.x * 32, r0 = blockIdx.y * 32;
    int tx = threadIdx.x, ty = threadIdx.y;
#pragma unroll
    for (int k = 0; k < 4; k++)
        tile[ty + 8 * k][tx] = src[(size_t)(r0 + ty + 8 * k) * cols + c0 + tx];
    __syncthreads();
#pragma unroll
    for (int k = 0; k < 4; k++)
        dst[(size_t)(c0 + ty + 8 * k) * rows + r0 + tx] = tile[tx][ty + 8 * k];
}

// ---------------- z-projection prep ----------------
__global__ void zp_kernel(const float* __restrict__ z, const float* __restrict__ bh) {
    __shared__ __align__(16) float zs[16 * DG];
    int t = blockIdx.x / 6, bc = blockIdx.x % 6;
    int j = threadIdx.x;
    const float* zsrc = z + ((size_t)t * BB + bc * 16) * DG;
    for (int idx = j; idx < 16 * DG; idx += NTH) zs[idx] = zsrc[idx];
    __syncthreads();
    float acc[16];
    float b0 = bh[j];
#pragma unroll
    for (int m = 0; m < 16; m++) acc[m] = b0;
    const float4* zs4 = (const float4*)zs;
    for (int i4 = 0; i4 < DG / 4; i4++) {
        float w0 = WGT_g[(size_t)(4 * i4 + 0) * DH + j];
        float w1 = WGT_g[(size_t)(4 * i4 + 1) * DH + j];
        float w2 = WGT_g[(size_t)(4 * i4 + 2) * DH + j];
        float w3 = WGT_g[(size_t)(4 * i4 + 3) * DH + j];
#pragma unroll
        for (int m = 0; m < 16; m++) {
            float4 zv = zs4[m * (DG / 4) + i4];
            acc[m] = fmaf(zv.x, w0, acc[m]);
            acc[m] = fmaf(zv.y, w1, acc[m]);
            acc[m] = fmaf(zv.z, w2, acc[m]);
            acc[m] = fmaf(zv.w, w3, acc[m]);
        }
    }
    float* dst = ZP_g + ((size_t)t * BB + bc * 16) * DH + j;
#pragma unroll
    for (int m = 0; m < 16; m++) dst[(size_t)m * DH] = acc[m];
}

// ---------------- main recurrence: cluster of 8 CTAs = 8 batches ----------------
// smem (floats): hist 47*384 | hsP 384*8 | hs_lin 384 | hbMine 384 | part 3072 |
//                dots 48 | lampow 48 | red 96
#define SMEM_FLOATS (47 * DH + DH * CL + DH + DH + 3072 + 48 + 48 + 96)

__global__ void __launch_bounds__(NTH, 1) __cluster_dims__(CL, 1, 1)
rnn_kernel(const float* __restrict__ lng, const float* __restrict__ lnb,
           const float* __restrict__ alpha, float* __restrict__ out) {
    extern __shared__ float sm[];
    float* hist   = sm;                    // 47*384   (own batch)
    float* hsP    = hist + 47 * DH;        // 384*8    layout [j][batch-in-cluster]
    float* hs_lin = hsP + DH * CL;         // 384      own batch hs (settle)
    float* hbMine = hs_lin + DH;           // 384      gathered hb slices
    float* part   = hbMine + DH;           // 8*48*8   gemv partials [jq][o][b]
    float* dots   = part + 3072;           // 48
    float* lampow = dots + 48;             // 48
    float* red    = lampow + 48;           // 96

    const int bglob = blockIdx.x;          // my batch (settle phase)
    const int rank  = blockIdx.x & (CL - 1);
    const int tid   = threadIdx.x;
    const int w     = tid >> 5, l = tid & 31;
    // gemv mapping: thread = (o, jq)
    const int o  = tid % SL;
    const int jq = tid / SL;               // 0..7
    // reduce mapping: thread = (ro, rb)
    const int ro = tid >> 3;               // 0..47
    const int rb = tid & 7;                // 0..7

    const uint32_t hbMine_u = smem_addr_u32(hbMine);
    const uint32_t hsP_u    = smem_addr_u32(hsP);

    float alf  = alpha[0];
    float kexp = (alf >= 0.f) ? (1.f + log1pf(expf(alf)))
                              : (1.f / (1.f + log1pf(expf(-alf))));
    float gj = lng[tid], bj = lnb[tid];

    if (tid < TT) lampow[tid] = ETA * powf(LAM, (float)tid);
    for (int i = tid; i < DH * CL; i += NTH) hsP[i] = 0.f;
    hs_lin[tid] = 0.f;
    __syncthreads();
    cluster_sync_();   // hsP zeros visible cluster-wide before first gemv

    const float* wp = WT_g + (size_t)(jq * SL) * DH + rank * SL + o;
    const ulonglong2* hpBase = (const ulonglong2*)(hsP + (size_t)(jq * SL) * CL);
    const int hbIdx = rank * SL + ro;     // index this thread's hb targets in peer rb

    float hcur = 0.f;

    for (int t = 0; t < TT; t++) {
        // ---------- gemv partial: out[o_glob][b] over j in my jq-chunk ----------
        unsigned long long acc0 = 0ull, acc1 = 0ull, acc2 = 0ull, acc3 = 0ull;
#pragma unroll 4
        for (int j = 0; j < SL; j++) {
            float wv = wp[(size_t)j * DH];
            unsigned long long w2 = pack2(wv, wv);
            ulonglong2 h01 = hpBase[j * 2];      // batches 0..3
            ulonglong2 h23 = hpBase[j * 2 + 1];  // batches 4..7
            acc0 = fma2(w2, h01.x, acc0);
            acc1 = fma2(w2, h01.y, acc1);
            acc2 = fma2(w2, h23.x, acc2);
            acc3 = fma2(w2, h23.y, acc3);
        }
        __syncthreads();   // prior part reads done (previous step)
        {
            ulonglong2* pp = (ulonglong2*)(part + (size_t)(jq * SL + o) * 8);
            ulonglong2 s01; s01.x = acc0; s01.y = acc1;
            ulonglong2 s23; s23.x = acc2; s23.y = acc3;
            pp[0] = s01; pp[1] = s23;
        }
        __syncthreads();
        {
            float hbv = 0.f;
#pragma unroll
            for (int q2 = 0; q2 < 8; q2++) hbv += part[q2 * 384 + ro * 8 + rb];
            // deliver to peer rb's hbMine[rank*48 + ro]
            st_cluster_f32(mapa_u32(hbMine_u + (uint32_t)hbIdx * 4, (uint32_t)rb), hbv);
        }
        cluster_sync_();   // all hb slices delivered

        // ---------- local: hb, LN1 ----------
        float hb = hbMine[tid] + ZP_g[((size_t)t * BB + bglob) * DH + tid];

        float s0 = hb, s1 = hb * hb;
#pragma unroll
        for (int oo = 16; oo; oo >>= 1) {
            s0 += __shfl_xor_sync(0xffffffffu, s0, oo);
            s1 += __shfl_xor_sync(0xffffffffu, s1, oo);
        }
        if (l == 0) { red[0 * NW + w] = s0; red[1 * NW + w] = s1; }
        __syncthreads();
        float Shb = 0.f, Shb2 = 0.f;
#pragma unroll
        for (int i = 0; i < NW; i++) { Shb += red[0 * NW + i]; Shb2 += red[1 * NW + i]; }
        float mean = Shb * (1.f / DH);
        float rstd = rsqrtf(Shb2 * (1.f / DH) - mean * mean + LN_EPS);
        hcur = fmaxf((hb - mean) * rstd * gj + bj, 0.f);
        hs_lin[tid] = hcur;
        __syncthreads();

        const bool fin   = (t == TT - 1);
        const int  nh    = fin ? (TT - 1) : t;
        const int  dbase = fin ? (TT - 2) : (t - 1);

        // ---------- settling loop (CTA-local) ----------
        for (int s = 0; s < 3; s++) {
            if (nh > 0) {
                float hsv[12];
#pragma unroll
                for (int i = 0; i < 12; i++) hsv[i] = hs_lin[l + 32 * i];
                for (int tau = w; tau < nh; tau += NW) {
                    const float* hr = hist + (size_t)tau * DH;
                    float d = 0.f;
#pragma unroll
                    for (int i = 0; i < 12; i++) d = fmaf(hr[l + 32 * i], hsv[i], d);
#pragma unroll
                    for (int oo = 16; oo; oo >>= 1) d += __shfl_xor_sync(0xffffffffu, d, oo);
                    if (l == 0) dots[tau] = d * lampow[dbase - tau];
                }
            }
            __syncthreads();

            float a0 = 0.f, a1 = 0.f, a2 = 0.f, a3 = 0.f;
            int tau = 0;
            for (; tau + 4 <= nh; tau += 4) {
                a0 = fmaf(dots[tau + 0], hist[(size_t)(tau + 0) * DH + tid], a0);
                a1 = fmaf(dots[tau + 1], hist[(size_t)(tau + 1) * DH + tid], a1);
                a2 = fmaf(dots[tau + 2], hist[(size_t)(tau + 2) * DH + tid], a2);
                a3 = fmaf(dots[tau + 3], hist[(size_t)(tau + 3) * DH + tid], a3);
            }
            for (; tau < nh; tau++)
                a0 = fmaf(dots[tau], hist[(size_t)tau * DH + tid], a0);
            float Ah = (a0 + a1) + (a2 + a3);

            float v0 = hcur * Ah, v1 = hcur * hcur, v2 = Ah * Ah, v3 = Ah, v4 = hb * Ah;
#pragma unroll
            for (int oo = 16; oo; oo >>= 1) {
                v0 += __shfl_xor_sync(0xffffffffu, v0, oo);
                v1 += __shfl_xor_sync(0xffffffffu, v1, oo);
                v2 += __shfl_xor_sync(0xffffffffu, v2, oo);
                v3 += __shfl_xor_sync(0xffffffffu, v3, oo);
                v4 += __shfl_xor_sync(0xffffffffu, v4, oo);
            }
            if (l == 0) {
                red[0 * NW + w] = v0; red[1 * NW + w] = v1; red[2 * NW + w] = v2;
                red[3 * NW + w] = v3; red[4 * NW + w] = v4;
            }
            __syncthreads();
            float D = 0.f, P = 0.f, Q = 0.f, SA = 0.f, SX = 0.f;
#pragma unroll
            for (int i = 0; i < NW; i++) {
                D += red[0 * NW + i]; P += red[1 * NW + i]; Q += red[2 * NW + i];
                SA += red[3 * NW + i]; SX += red[4 * NW + i];
            }
            float c1, ca;
            if (!fin) {
                float n1 = fmaxf(sqrtf(P), 1e-6f);
                float n2 = fmaxf(sqrtf(Q), 1e-6f);
                float R  = fminf(fmaxf(D / (n1 * n2), 0.f), 1.f);
                float a  = 1.f - exp2f(kexp * log2f(1.f - R));
                c1 = 1.f - a * a;
                ca = a;
            } else { c1 = 1.f; ca = 1.f; }
            float Sv  = c1 * Shb + ca * SA;
            float Sv2 = c1 * c1 * Shb2 + 2.f * c1 * ca * SX + ca * ca * Q;
            float mn  = Sv * (1.f / DH);
            float rs  = rsqrtf(Sv2 * (1.f / DH) - mn * mn + LN_EPS);
            float v   = c1 * hb + ca * Ah;
            hcur = fmaxf((v - mn) * rs * gj + bj, 0.f);
            hs_lin[tid] = hcur;
            __syncthreads();
        }
        if (!fin) hist[(size_t)t * DH + tid] = hcur;

        // ---------- broadcast my hs to all cluster CTAs' hsP[:, rank] ----------
        {
            uint32_t off = (uint32_t)(tid * CL + rank) * 4;
#pragma unroll
            for (int p = 0; p < CL; p++)
                st_cluster_f32(mapa_u32(hsP_u + off, (uint32_t)p), hcur);
        }
        cluster_sync_();   // hsP complete everywhere for next gemv
    }

    out[(size_t)bglob * DH + tid] = hcur;
}

// ---------------- launch ----------------
extern "C" void kernel_launch(void* const* d_in, const int* in_sizes, int n_in,
                              void* d_out, int out_size) {
    const float* z     = (const float*)d_in[0];
    const float* Wh    = (const float*)d_in[1];
    const float* Wg    = (const float*)d_in[2];
    const float* bh    = (const float*)d_in[3];
    const float* lng   = (const float*)d_in[4];
    const float* lnb   = (const float*)d_in[5];
    const float* alpha = (const float*)d_in[6];
    float* out = (float*)d_out;

    const int smem_bytes = SMEM_FLOATS * 4;
    static int configured = 0;
    if (!configured) {
        cudaFuncSetAttribute(rnn_kernel, cudaFuncAttributeMaxDynamicSharedMemorySize, smem_bytes);
        configured = 1;
    }

    transpose_k<<<dim3(12, 12), dim3(32, 8)>>>(Wh, DH, DH, 0);  // -> WT_g
    transpose_k<<<dim3(6, 12), dim3(32, 8)>>>(Wg, DH, DG, 1);   // -> WGT_g
    zp_kernel<<<TT * 6, NTH>>>(z, bh);
    rnn_kernel<<<BB, NTH, smem_bytes>>>(lng, lnb, alpha, out);
}

// round 6
// speedup vs baseline: 1.5266x; 1.5266x over previous
#include <cuda_runtime.h>
#include <cuda_bf16.h>
#include <cstdint>

#define DH 384
#define DG 192
#define TT 48
#define BB 96
#define NTH 384
#define NW 12
#define LAM 0.9f
#define ETA 0.5f
#define LN_EPS 1e-5f

typedef unsigned long long ull;

// ---------------- device scratch (allocation-free rule) ----------------
__device__ float WT_g[DH * DH];              // W_h transposed: WT[j*DH + o] = W_h[o*DH + j]
__device__ float WGT_g[DG * DH];             // W_g transposed
__device__ float ZP_g[(size_t)TT * BB * DH]; // z @ W_g^T + b_h

// ---------------- helpers ----------------
__device__ __forceinline__ float wred(float v) {
#pragma unroll
    for (int o = 16; o; o >>= 1) v += __shfl_xor_sync(0xffffffffu, v, o);
    return v;
}
__device__ __forceinline__ ull fma2(ull a, ull b, ull c) {
    ull d;
    asm("fma.rn.f32x2 %0, %1, %2, %3;" : "=l"(d) : "l"(a), "l"(b), "l"(c));
    return d;
}
__device__ __forceinline__ ull pack2(float lo, float hi) {
    ull d;
    asm("mov.b64 %0, {%1, %2};" : "=l"(d) : "f"(lo), "f"(hi));
    return d;
}
__device__ __forceinline__ ull splat2(float x) {
    ull d;
    asm("mov.b64 %0, {%1, %1};" : "=l"(d) : "f"(x));
    return d;
}
__device__ __forceinline__ float2 unpack2(ull v) {
    float lo, hi;
    asm("mov.b64 {%0, %1}, %2;" : "=f"(lo), "=f"(hi) : "l"(v));
    return make_float2(lo, hi);
}

// ---------------- transpose prep ----------------
__global__ void transpose_k(const float* __restrict__ src, int rows, int cols, int which) {
    __shared__ float tile[32][33];
    float* dst = (which == 0) ? WT_g : WGT_g;
    int c0 = blockIdx.x * 32, r0 = blockIdx.y * 32;
    int tx = threadIdx.x, ty = threadIdx.y;
#pragma unroll
    for (int k = 0; k < 4; k++)
        tile[ty + 8 * k][tx] = src[(size_t)(r0 + ty + 8 * k) * cols + c0 + tx];
    __syncthreads();
#pragma unroll
    for (int k = 0; k < 4; k++)
        dst[(size_t)(c0 + ty + 8 * k) * rows + r0 + tx] = tile[tx][ty + 8 * k];
}

// ---------------- z-projection prep (f32x2) ----------------
__global__ void zp_kernel(const float* __restrict__ z, const float* __restrict__ bh) {
    __shared__ float zt[DG * 18];   // transposed: zt[i*18 + m]
    int t = blockIdx.x / 6, bc = blockIdx.x % 6;
    int j = threadIdx.x;
    const float* zsrc = z + ((size_t)t * BB + bc * 16) * DG;
    for (int idx = j; idx < 16 * DG; idx += NTH) {
        int m = idx / DG, i = idx % DG;
        zt[i * 18 + m] = zsrc[idx];
    }
    __syncthreads();
    ull acc[8];
    ull b2 = splat2(bh[j]);
#pragma unroll
    for (int p = 0; p < 8; p++) acc[p] = b2;
    for (int i = 0; i < DG; i++) {
        ull ws = splat2(WGT_g[(size_t)i * DH + j]);
        const ull* z2 = (const ull*)(zt + i * 18);
#pragma unroll
        for (int p = 0; p < 8; p++) acc[p] = fma2(ws, z2[p], acc[p]);
    }
    float* dst = ZP_g + ((size_t)t * BB + bc * 16) * DH + j;
#pragma unroll
    for (int p = 0; p < 8; p++) {
        float2 f = unpack2(acc[p]);
        dst[(size_t)(2 * p + 0) * DH] = f.x;
        dst[(size_t)(2 * p + 1) * DH] = f.y;
    }
}

// ---------------- main recurrence: one CTA per batch ----------------
__global__ void __launch_bounds__(NTH, 1)
rnn_kernel(const float* __restrict__ lng, const float* __restrict__ lnb,
           const float* __restrict__ alpha, float* __restrict__ out) {
    __shared__ float hist[47 * DH];                 // history (dots phase)
    __shared__ float hs_lin[DH];                    // current h (gemv + dots)
    __shared__ float part[4 * DH];                  // gemv partials
    __shared__ __align__(16) float dots_s[48];      // scaled dot coefficients
    __shared__ float lampow[48];
    __shared__ __align__(16) float red[2][12];      // LN1 partials
    __shared__ __align__(16) float p5[5][12];       // fused gate/LN partials

    const int b = blockIdx.x;
    const int tid = threadIdx.x;
    const int w = tid >> 5, l = tid & 31;
    const int q = tid / 96, c = tid % 96;

    float alf = alpha[0];
    float kexp = (alf >= 0.f) ? (1.f + log1pf(expf(alf)))
                              : (1.f / (1.f + log1pf(expf(-alf))));
    float gj = lng[tid], bj = lnb[tid];

    if (tid < 48) { lampow[tid] = ETA * powf(LAM, (float)tid); dots_s[tid] = 0.f; }
    hs_lin[tid] = 0.f;

    float hreg[47];
#pragma unroll
    for (int i = 0; i < 47; i++) hreg[i] = 0.f;
    __syncthreads();

    const float4* WT4 = (const float4*)WT_g;
    const float4* hs4 = (const float4*)hs_lin;
    float hcur = 0.f;

    for (int t = 0; t < TT; t++) {
        // ---------- gemv: hb = W_h @ hs + ZP[t][b] (f32x2 packed) ----------
        float zp = ZP_g[((size_t)t * BB + b) * DH + tid];
        ull aXY = 0ull, aZW = 0ull;
        const int jb = q * 24;
#pragma unroll 6
        for (int jj = 0; jj < 24; jj++) {
            float4 hv = hs4[jb + jj];
            int j0 = (jb + jj) * 4;
            float4 w0 = WT4[(size_t)(j0 + 0) * 96 + c];
            float4 w1 = WT4[(size_t)(j0 + 1) * 96 + c];
            float4 w2 = WT4[(size_t)(j0 + 2) * 96 + c];
            float4 w3 = WT4[(size_t)(j0 + 3) * 96 + c];
            ull h0 = splat2(hv.x), h1 = splat2(hv.y), h2 = splat2(hv.z), h3 = splat2(hv.w);
            aXY = fma2(h0, pack2(w0.x, w0.y), aXY);
            aZW = fma2(h0, pack2(w0.z, w0.w), aZW);
            aXY = fma2(h1, pack2(w1.x, w1.y), aXY);
            aZW = fma2(h1, pack2(w1.z, w1.w), aZW);
            aXY = fma2(h2, pack2(w2.x, w2.y), aXY);
            aZW = fma2(h2, pack2(w2.z, w2.w), aZW);
            aXY = fma2(h3, pack2(w3.x, w3.y), aXY);
            aZW = fma2(h3, pack2(w3.z, w3.w), aZW);
        }
        {
            ulonglong2 st2; st2.x = aXY; st2.y = aZW;
            ((ulonglong2*)part)[tid] = st2;   // part[q*384 + 4c .. +3]
        }
        __syncthreads();
        float hb = zp;
#pragma unroll
        for (int qq = 0; qq < 4; qq++) hb += part[qq * DH + tid];

        // ---------- LN#1 ----------
        float s0 = wred(hb);
        float s1 = wred(hb * hb);
        if (l == 0) { red[0][w] = s0; red[1][w] = s1; }
        __syncthreads();
        float Shb = 0.f, Shb2 = 0.f;
        {
            const float4* r0 = (const float4*)red[0];
            const float4* r1 = (const float4*)red[1];
#pragma unroll
            for (int i = 0; i < 3; i++) {
                float4 a = r0[i], bq = r1[i];
                Shb  += (a.x + a.y) + (a.z + a.w);
                Shb2 += (bq.x + bq.y) + (bq.z + bq.w);
            }
        }
        float mean = Shb * (1.f / DH);
        float rstd = rsqrtf(Shb2 * (1.f / DH) - mean * mean + LN_EPS);
        hcur = fmaxf((hb - mean) * rstd * gj + bj, 0.f);
        hs_lin[tid] = hcur;   // for dots phase
        __syncthreads();

        const bool fin   = (t == TT - 1);
        const int  nh    = fin ? 47 : t;
        const int  dbase = fin ? 46 : (t - 1);

        // ---------- settling loop ----------
        for (int s = 0; s < 3; s++) {
            // dots[tau] = eta*lam^(dbase-tau) * (hist[tau] . hs)   (warp-parallel over tau)
            if (nh > 0) {
                float hsv[12];
#pragma unroll
                for (int i = 0; i < 12; i++) hsv[i] = hs_lin[l + 32 * i];
                for (int tau = w; tau < nh; tau += NW) {
                    const float* hr = hist + (size_t)tau * DH;
                    float d = 0.f;
#pragma unroll
                    for (int i = 0; i < 12; i++) d = fmaf(hr[l + 32 * i], hsv[i], d);
                    d = wred(d);
                    if (l == 0) dots_s[tau] = d * lampow[dbase - tau];
                }
            }
            __syncthreads();

            // Ah[tid] = sum_tau dots[tau]*hreg[tau]  (register FMAs, vector dot loads)
            float dv[48];
            {
                const float4* d4 = (const float4*)dots_s;
#pragma unroll
                for (int i = 0; i < 12; i++) {
                    float4 v = d4[i];
                    dv[4 * i] = v.x; dv[4 * i + 1] = v.y; dv[4 * i + 2] = v.z; dv[4 * i + 3] = v.w;
                }
            }
            float A0 = 0.f, A1 = 0.f, A2 = 0.f, A3 = 0.f;
#pragma unroll
            for (int tau = 0; tau < 47; tau += 4) {
                A0 = fmaf(dv[tau], hreg[tau], A0);
                if (tau + 1 < 47) A1 = fmaf(dv[tau + 1], hreg[tau + 1], A1);
                if (tau + 2 < 47) A2 = fmaf(dv[tau + 2], hreg[tau + 2], A2);
                if (tau + 3 < 47) A3 = fmaf(dv[tau + 3], hreg[tau + 3], A3);
            }
            float Ah = (A0 + A1) + (A2 + A3);

            // fused gate + LN reduction: 5 sums, one shuffle round
            float r0 = wred(hcur * Ah);
            float r1 = wred(hcur * hcur);
            float r2 = wred(Ah * Ah);
            float r3 = wred(Ah);
            float r4 = wred(hb * Ah);
            if (l == 0) {
                p5[0][w] = r0; p5[1][w] = r1; p5[2][w] = r2; p5[3][w] = r3; p5[4][w] = r4;
            }
            __syncthreads();
            float S[5];
#pragma unroll
            for (int v = 0; v < 5; v++) {
                const float4* pv = (const float4*)p5[v];
                float4 x = pv[0], y = pv[1], zq = pv[2];
                S[v] = ((x.x + x.y) + (x.z + x.w)) + ((y.x + y.y) + (y.z + y.w))
                     + ((zq.x + zq.y) + (zq.z + zq.w));
            }
            float D = S[0], P = S[1], Q = S[2], SA = S[3], SX = S[4];

            float c1, ca;
            if (!fin) {
                float n1 = fmaxf(sqrtf(P), 1e-6f);
                float n2 = fmaxf(sqrtf(Q), 1e-6f);
                float R  = fminf(fmaxf(D / (n1 * n2), 0.f), 1.f);
                float a  = 1.f - exp2f(kexp * log2f(1.f - R));
                c1 = 1.f - a * a;
                ca = a;
            } else { c1 = 1.f; ca = 1.f; }
            float Sv  = c1 * Shb + ca * SA;
            float Sv2 = c1 * c1 * Shb2 + 2.f * c1 * ca * SX + ca * ca * Q;
            float mn  = Sv * (1.f / DH);
            float rs  = rsqrtf(Sv2 * (1.f / DH) - mn * mn + LN_EPS);
            hcur = fmaxf((c1 * hb + ca * Ah - mn) * rs * gj + bj, 0.f);
            __syncthreads();          // dots_s/hs_lin consumers done
            hs_lin[tid] = hcur;
            __syncthreads();          // hs_lin ready for next dots
        }

        if (!fin) {
            hist[(size_t)t * DH + tid] = hcur;
#pragma unroll
            for (int i = 0; i < 47; i++)
                if (i == t) hreg[i] = hcur;
        }
        __syncthreads();
    }
    out[(size_t)b * DH + tid] = hcur;
}

// ---------------- launch ----------------
extern "C" void kernel_launch(void* const* d_in, const int* in_sizes, int n_in,
                              void* d_out, int out_size) {
    const float* z     = (const float*)d_in[0];  // [48,96,192]
    const float* Wh    = (const float*)d_in[1];  // [384,384]
    const float* Wg    = (const float*)d_in[2];  // [384,192]
    const float* bh    = (const float*)d_in[3];  // [384]
    const float* lng   = (const float*)d_in[4];  // [384]
    const float* lnb   = (const float*)d_in[5];  // [384]
    const float* alpha = (const float*)d_in[6];  // [1]
    float* out = (float*)d_out;                  // [96,384]

    transpose_k<<<dim3(12, 12), dim3(32, 8)>>>(Wh, DH, DH, 0);  // -> WT_g
    transpose_k<<<dim3(6, 12), dim3(32, 8)>>>(Wg, DH, DG, 1);   // -> WGT_g
    zp_kernel<<<TT * 6, NTH>>>(z, bh);
    rnn_kernel<<<BB, NTH>>>(lng, lnb, alpha, out);
}